// round 1
// baseline (speedup 1.0000x reference)
#include <cuda_runtime.h>

// ---------------- problem constants ----------------
#define T_TOK   8192          // B*S tokens
#define D_DIM   1024
#define FF_DIM  4096
#define E_NUM   16
#define K_TOP   2
#define EPS     1e-6f

#define BM 128
#define BN 128
#define BK 8
#define ROWS_MAX 18432        // T*K + E*pad headroom (16384 + 2048)

// ---------------- scratch (device globals; no cudaMalloc allowed) ----------------
__device__ float g_xn[(size_t)T_TOK * D_DIM];                 // normalized tokens
__device__ float g_h [(size_t)ROWS_MAX * FF_DIM];             // expert hidden (relu(x@wi))
__device__ float g_y [(size_t)ROWS_MAX * D_DIM];              // expert output (scaled)
__device__ int   g_cnt [E_NUM];
__device__ int   g_cnt2[E_NUM];
__device__ int   g_off [E_NUM + 1];
__device__ int   g_row_token[ROWS_MAX];
__device__ float g_row_scale[ROWS_MAX];
__device__ int   g_tok_row[T_TOK * K_TOP];
__device__ int   g_tok_e  [T_TOK * K_TOP];
__device__ float g_tok_s  [T_TOK * K_TOP];

// ---------------- reset (graph replays reuse scratch) ----------------
__global__ void reset_kernel() {
    int i = blockIdx.x * blockDim.x + threadIdx.x;
    if (i < ROWS_MAX) g_row_token[i] = -1;
    if (i < E_NUM) { g_cnt[i] = 0; g_cnt2[i] = 0; }
}

// ---------------- RMSNorm: one block per token ----------------
__global__ __launch_bounds__(256) void rmsnorm_kernel(const float* __restrict__ x,
                                                      const float* __restrict__ w) {
    int t = blockIdx.x;
    int tid = threadIdx.x;
    const float4* xr = (const float4*)(x + (size_t)t * D_DIM);
    float4 v = xr[tid];
    float ss = v.x * v.x + v.y * v.y + v.z * v.z + v.w * v.w;

    __shared__ float red[256];
    red[tid] = ss;
    __syncthreads();
    for (int s = 128; s > 0; s >>= 1) {
        if (tid < s) red[tid] += red[tid + s];
        __syncthreads();
    }
    float inv = rsqrtf(red[0] * (1.0f / (float)D_DIM) + EPS);

    float4 wv = ((const float4*)w)[tid];
    float4 o;
    o.x = v.x * inv * wv.x;
    o.y = v.y * inv * wv.y;
    o.z = v.z * inv * wv.z;
    o.w = v.w * inv * wv.w;
    ((float4*)(g_xn + (size_t)t * D_DIM))[tid] = o;
}

// ---------------- gate: one warp per token, 16 logits, top-2 softmax ----------------
__global__ __launch_bounds__(256) void gate_kernel(const float* __restrict__ gw,
                                                   const float* __restrict__ gb) {
    int t = blockIdx.x * 8 + (threadIdx.x >> 5);
    int lane = threadIdx.x & 31;
    if (t >= T_TOK) return;

    float acc[E_NUM];
#pragma unroll
    for (int e = 0; e < E_NUM; e++) acc[e] = 0.0f;

    const float* xr = g_xn + (size_t)t * D_DIM;
    for (int d = lane; d < D_DIM; d += 32) {
        float xv = xr[d];
        const float4* wr = (const float4*)(gw + (size_t)d * E_NUM);
        float4 w0 = wr[0], w1 = wr[1], w2 = wr[2], w3 = wr[3];
        acc[0]  += xv * w0.x; acc[1]  += xv * w0.y; acc[2]  += xv * w0.z; acc[3]  += xv * w0.w;
        acc[4]  += xv * w1.x; acc[5]  += xv * w1.y; acc[6]  += xv * w1.z; acc[7]  += xv * w1.w;
        acc[8]  += xv * w2.x; acc[9]  += xv * w2.y; acc[10] += xv * w2.z; acc[11] += xv * w2.w;
        acc[12] += xv * w3.x; acc[13] += xv * w3.y; acc[14] += xv * w3.z; acc[15] += xv * w3.w;
    }
#pragma unroll
    for (int e = 0; e < E_NUM; e++) {
#pragma unroll
        for (int o = 16; o > 0; o >>= 1)
            acc[e] += __shfl_down_sync(0xFFFFFFFFu, acc[e], o);
    }

    if (lane == 0) {
        float v0 = -1e30f, v1 = -1e30f;
        int e0 = 0, e1 = 0;
#pragma unroll
        for (int e = 0; e < E_NUM; e++) {
            float val = acc[e] + gb[e];
            if (val > v0) { v1 = v0; e1 = e0; v0 = val; e0 = e; }
            else if (val > v1) { v1 = val; e1 = e; }
        }
        float ex = expf(v1 - v0);
        float s0 = 1.0f / (1.0f + ex);
        float s1 = ex * s0;
        g_tok_e[2 * t + 0] = e0; g_tok_s[2 * t + 0] = s0;
        g_tok_e[2 * t + 1] = e1; g_tok_s[2 * t + 1] = s1;
        atomicAdd(&g_cnt[e0], 1);
        atomicAdd(&g_cnt[e1], 1);
    }
}

// ---------------- padded prefix offsets ----------------
__global__ void offsets_kernel() {
    if (threadIdx.x == 0 && blockIdx.x == 0) {
        int o = 0;
        for (int e = 0; e < E_NUM; e++) {
            g_off[e] = o;
            o += ((g_cnt[e] + BM - 1) / BM) * BM;
        }
        g_off[E_NUM] = o;
    }
}

// ---------------- scatter tokens into expert row lists ----------------
__global__ __launch_bounds__(256) void scatter_kernel() {
    int t = blockIdx.x * blockDim.x + threadIdx.x;
    if (t >= T_TOK) return;
#pragma unroll
    for (int k = 0; k < K_TOP; k++) {
        int e = g_tok_e[2 * t + k];
        int r = g_off[e] + atomicAdd(&g_cnt2[e], 1);
        g_row_token[r] = t;
        g_row_scale[r] = g_tok_s[2 * t + k];
        g_tok_row[2 * t + k] = r;
    }
}

// ---------------- grouped SGEMM 1: h = relu(xn[gather] @ wi[e]) ----------------
__global__ __launch_bounds__(256) void gemm1_kernel(const float* __restrict__ wi) {
    int r0 = blockIdx.y * BM;
    int n0 = blockIdx.x * BN;
    if (r0 >= g_off[E_NUM]) return;
    if (g_row_token[r0] < 0) return;     // fully padded tile

    int e = 0;
    while (r0 >= g_off[e + 1]) e++;
    const float* B = wi + (size_t)e * D_DIM * FF_DIM;

    __shared__ float As[BK][BM];
    __shared__ float Bs[BK][BN];
    __shared__ int   s_tok[BM];

    int tid = threadIdx.x;
    if (tid < BM) s_tok[tid] = g_row_token[r0 + tid];
    __syncthreads();

    int tx = tid & 15, ty = tid >> 4;
    int arow = tid >> 1, ak4 = (tid & 1) * 4;
    int brow = tid >> 5, bcol = (tid & 31) * 4;

    int atok = s_tok[arow];
    const float* aptr = g_xn + (size_t)(atok >= 0 ? atok : 0) * D_DIM;

    float c[8][8];
#pragma unroll
    for (int i = 0; i < 8; i++)
#pragma unroll
        for (int j = 0; j < 8; j++) c[i][j] = 0.0f;

    for (int k0 = 0; k0 < D_DIM; k0 += BK) {
        float4 av = *(const float4*)(aptr + k0 + ak4);
        float4 bv = *(const float4*)(B + (size_t)(k0 + brow) * FF_DIM + n0 + bcol);
        As[ak4 + 0][arow] = av.x;
        As[ak4 + 1][arow] = av.y;
        As[ak4 + 2][arow] = av.z;
        As[ak4 + 3][arow] = av.w;
        *(float4*)&Bs[brow][bcol] = bv;
        __syncthreads();
#pragma unroll
        for (int k = 0; k < BK; k++) {
            float a[8], b[8];
            *(float4*)(a)     = *(const float4*)&As[k][ty * 8];
            *(float4*)(a + 4) = *(const float4*)&As[k][ty * 8 + 4];
            *(float4*)(b)     = *(const float4*)&Bs[k][tx * 8];
            *(float4*)(b + 4) = *(const float4*)&Bs[k][tx * 8 + 4];
#pragma unroll
            for (int i = 0; i < 8; i++)
#pragma unroll
                for (int j = 0; j < 8; j++) c[i][j] += a[i] * b[j];
        }
        __syncthreads();
    }

#pragma unroll
    for (int i = 0; i < 8; i++) {
        int lr = ty * 8 + i;
        if (s_tok[lr] < 0) continue;
        size_t base = (size_t)(r0 + lr) * FF_DIM + n0 + tx * 8;
        float4 o0, o1;
        o0.x = fmaxf(c[i][0], 0.f); o0.y = fmaxf(c[i][1], 0.f);
        o0.z = fmaxf(c[i][2], 0.f); o0.w = fmaxf(c[i][3], 0.f);
        o1.x = fmaxf(c[i][4], 0.f); o1.y = fmaxf(c[i][5], 0.f);
        o1.z = fmaxf(c[i][6], 0.f); o1.w = fmaxf(c[i][7], 0.f);
        *(float4*)&g_h[base]     = o0;
        *(float4*)&g_h[base + 4] = o1;
    }
}

// ---------------- grouped SGEMM 2: y = scale * (h @ wo[e]) ----------------
__global__ __launch_bounds__(256) void gemm2_kernel(const float* __restrict__ wo) {
    int r0 = blockIdx.y * BM;
    int n0 = blockIdx.x * BN;
    if (r0 >= g_off[E_NUM]) return;
    if (g_row_token[r0] < 0) return;

    int e = 0;
    while (r0 >= g_off[e + 1]) e++;
    const float* B = wo + (size_t)e * FF_DIM * D_DIM;

    __shared__ float As[BK][BM];
    __shared__ float Bs[BK][BN];

    int tid = threadIdx.x;
    int tx = tid & 15, ty = tid >> 4;
    int arow = tid >> 1, ak4 = (tid & 1) * 4;
    int brow = tid >> 5, bcol = (tid & 31) * 4;

    const float* aptr = g_h + (size_t)(r0 + arow) * FF_DIM;

    float c[8][8];
#pragma unroll
    for (int i = 0; i < 8; i++)
#pragma unroll
        for (int j = 0; j < 8; j++) c[i][j] = 0.0f;

    for (int k0 = 0; k0 < FF_DIM; k0 += BK) {
        float4 av = *(const float4*)(aptr + k0 + ak4);
        float4 bv = *(const float4*)(B + (size_t)(k0 + brow) * D_DIM + n0 + bcol);
        As[ak4 + 0][arow] = av.x;
        As[ak4 + 1][arow] = av.y;
        As[ak4 + 2][arow] = av.z;
        As[ak4 + 3][arow] = av.w;
        *(float4*)&Bs[brow][bcol] = bv;
        __syncthreads();
#pragma unroll
        for (int k = 0; k < BK; k++) {
            float a[8], b[8];
            *(float4*)(a)     = *(const float4*)&As[k][ty * 8];
            *(float4*)(a + 4) = *(const float4*)&As[k][ty * 8 + 4];
            *(float4*)(b)     = *(const float4*)&Bs[k][tx * 8];
            *(float4*)(b + 4) = *(const float4*)&Bs[k][tx * 8 + 4];
#pragma unroll
            for (int i = 0; i < 8; i++)
#pragma unroll
                for (int j = 0; j < 8; j++) c[i][j] += a[i] * b[j];
        }
        __syncthreads();
    }

#pragma unroll
    for (int i = 0; i < 8; i++) {
        int lr = ty * 8 + i;
        float sc = g_row_scale[r0 + lr];
        size_t base = (size_t)(r0 + lr) * D_DIM + n0 + tx * 8;
        float4 o0, o1;
        o0.x = sc * c[i][0]; o0.y = sc * c[i][1]; o0.z = sc * c[i][2]; o0.w = sc * c[i][3];
        o1.x = sc * c[i][4]; o1.y = sc * c[i][5]; o1.z = sc * c[i][6]; o1.w = sc * c[i][7];
        *(float4*)&g_y[base]     = o0;
        *(float4*)&g_y[base + 4] = o1;
    }
}

// ---------------- combine: out = hidden + y[row0] + y[row1] ----------------
__global__ __launch_bounds__(256) void combine_kernel(const float* __restrict__ hidden,
                                                      float* __restrict__ out) {
    int i = blockIdx.x * blockDim.x + threadIdx.x;   // over T*D/4 float4s
    int t = i >> 8;                                   // D/4 = 256 float4s per token
    int d4 = i & 255;
    int r0 = g_tok_row[2 * t + 0];
    int r1 = g_tok_row[2 * t + 1];
    float4 h  = ((const float4*)hidden)[i];
    float4 y0 = ((const float4*)(g_y + (size_t)r0 * D_DIM))[d4];
    float4 y1 = ((const float4*)(g_y + (size_t)r1 * D_DIM))[d4];
    float4 o;
    o.x = h.x + y0.x + y1.x;
    o.y = h.y + y0.y + y1.y;
    o.z = h.z + y0.z + y1.z;
    o.w = h.w + y0.w + y1.w;
    ((float4*)out)[i] = o;
}

// ---------------- launch ----------------
extern "C" void kernel_launch(void* const* d_in, const int* in_sizes, int n_in,
                              void* d_out, int out_size) {
    const float* hidden = (const float*)d_in[0];
    const float* ln_w   = (const float*)d_in[1];
    const float* gate_w = (const float*)d_in[2];
    const float* gate_b = (const float*)d_in[3];
    const float* wi     = (const float*)d_in[4];
    const float* wo     = (const float*)d_in[5];
    float* out = (float*)d_out;

    reset_kernel<<<(ROWS_MAX + 255) / 256, 256>>>();
    rmsnorm_kernel<<<T_TOK, 256>>>(hidden, ln_w);
    gate_kernel<<<T_TOK / 8, 256>>>(gate_w, gate_b);
    offsets_kernel<<<1, 32>>>();
    scatter_kernel<<<(T_TOK + 255) / 256, 256>>>();
    gemm1_kernel<<<dim3(FF_DIM / BN, ROWS_MAX / BM), 256>>>(wi);
    gemm2_kernel<<<dim3(D_DIM / BN, ROWS_MAX / BM), 256>>>(wo);
    combine_kernel<<<(T_TOK * D_DIM / 4) / 256, 256>>>(hidden, out);
}

// round 2
// speedup vs baseline: 2.0591x; 2.0591x over previous
#include <cuda_runtime.h>

// ---------------- problem constants ----------------
#define T_TOK   8192          // B*S tokens
#define D_DIM   1024
#define FF_DIM  4096
#define E_NUM   16
#define K_TOP   2
#define EPS     1e-6f

#define BM 128
#define BN 128
#define BK 32
#define ROWS_MAX 18432        // T*K + E*pad headroom (16384 + 2048)

// ---------------- scratch (device globals; no cudaMalloc allowed) ----------------
__device__ float g_xn[(size_t)T_TOK * D_DIM];                 // normalized tokens
__device__ float g_h [(size_t)ROWS_MAX * FF_DIM];             // expert hidden (relu(x@wi))
__device__ float g_y [(size_t)ROWS_MAX * D_DIM];              // expert output (scaled)
__device__ int   g_cnt [E_NUM];
__device__ int   g_cnt2[E_NUM];
__device__ int   g_off [E_NUM + 1];
__device__ int   g_row_token[ROWS_MAX];
__device__ float g_row_scale[ROWS_MAX];
__device__ int   g_tok_row[T_TOK * K_TOP];
__device__ int   g_tok_e  [T_TOK * K_TOP];
__device__ float g_tok_s  [T_TOK * K_TOP];

// ---------------- helpers ----------------
__device__ __forceinline__ float f2tf32(float x) {
    unsigned r;
    asm("cvt.rna.tf32.f32 %0, %1;" : "=r"(r) : "f"(x));
    return __uint_as_float(r);
}
__device__ __forceinline__ float4 cvt4(float4 v) {
    float4 o;
    o.x = f2tf32(v.x); o.y = f2tf32(v.y); o.z = f2tf32(v.z); o.w = f2tf32(v.w);
    return o;
}
__device__ __forceinline__ void mma_tf32(float* c, const unsigned* a, const unsigned* b) {
    asm volatile(
        "mma.sync.aligned.m16n8k8.row.col.f32.tf32.tf32.f32 "
        "{%0,%1,%2,%3}, {%4,%5,%6,%7}, {%8,%9}, {%0,%1,%2,%3};"
        : "+f"(c[0]), "+f"(c[1]), "+f"(c[2]), "+f"(c[3])
        : "r"(a[0]), "r"(a[1]), "r"(a[2]), "r"(a[3]), "r"(b[0]), "r"(b[1]));
}

// ---------------- reset ----------------
__global__ void reset_kernel() {
    int i = blockIdx.x * blockDim.x + threadIdx.x;
    if (i < ROWS_MAX) g_row_token[i] = -1;
    if (i < E_NUM) { g_cnt[i] = 0; g_cnt2[i] = 0; }
}

// ---------------- RMSNorm ----------------
__global__ __launch_bounds__(256) void rmsnorm_kernel(const float* __restrict__ x,
                                                      const float* __restrict__ w) {
    int t = blockIdx.x;
    int tid = threadIdx.x;
    const float4* xr = (const float4*)(x + (size_t)t * D_DIM);
    float4 v = xr[tid];
    float ss = v.x * v.x + v.y * v.y + v.z * v.z + v.w * v.w;

    __shared__ float red[256];
    red[tid] = ss;
    __syncthreads();
    for (int s = 128; s > 0; s >>= 1) {
        if (tid < s) red[tid] += red[tid + s];
        __syncthreads();
    }
    float inv = rsqrtf(red[0] * (1.0f / (float)D_DIM) + EPS);

    float4 wv = ((const float4*)w)[tid];
    float4 o;
    o.x = v.x * inv * wv.x;
    o.y = v.y * inv * wv.y;
    o.z = v.z * inv * wv.z;
    o.w = v.w * inv * wv.w;
    ((float4*)(g_xn + (size_t)t * D_DIM))[tid] = o;
}

// ---------------- gate ----------------
__global__ __launch_bounds__(256) void gate_kernel(const float* __restrict__ gw,
                                                   const float* __restrict__ gb) {
    int t = blockIdx.x * 8 + (threadIdx.x >> 5);
    int lane = threadIdx.x & 31;
    if (t >= T_TOK) return;

    float acc[E_NUM];
#pragma unroll
    for (int e = 0; e < E_NUM; e++) acc[e] = 0.0f;

    const float* xr = g_xn + (size_t)t * D_DIM;
    for (int d = lane; d < D_DIM; d += 32) {
        float xv = xr[d];
        const float4* wr = (const float4*)(gw + (size_t)d * E_NUM);
        float4 w0 = wr[0], w1 = wr[1], w2 = wr[2], w3 = wr[3];
        acc[0]  += xv * w0.x; acc[1]  += xv * w0.y; acc[2]  += xv * w0.z; acc[3]  += xv * w0.w;
        acc[4]  += xv * w1.x; acc[5]  += xv * w1.y; acc[6]  += xv * w1.z; acc[7]  += xv * w1.w;
        acc[8]  += xv * w2.x; acc[9]  += xv * w2.y; acc[10] += xv * w2.z; acc[11] += xv * w2.w;
        acc[12] += xv * w3.x; acc[13] += xv * w3.y; acc[14] += xv * w3.z; acc[15] += xv * w3.w;
    }
#pragma unroll
    for (int e = 0; e < E_NUM; e++) {
#pragma unroll
        for (int o = 16; o > 0; o >>= 1)
            acc[e] += __shfl_down_sync(0xFFFFFFFFu, acc[e], o);
    }

    if (lane == 0) {
        float v0 = -1e30f, v1 = -1e30f;
        int e0 = 0, e1 = 0;
#pragma unroll
        for (int e = 0; e < E_NUM; e++) {
            float val = acc[e] + gb[e];
            if (val > v0) { v1 = v0; e1 = e0; v0 = val; e0 = e; }
            else if (val > v1) { v1 = val; e1 = e; }
        }
        float ex = expf(v1 - v0);
        float s0 = 1.0f / (1.0f + ex);
        float s1 = ex * s0;
        g_tok_e[2 * t + 0] = e0; g_tok_s[2 * t + 0] = s0;
        g_tok_e[2 * t + 1] = e1; g_tok_s[2 * t + 1] = s1;
        atomicAdd(&g_cnt[e0], 1);
        atomicAdd(&g_cnt[e1], 1);
    }
}

// ---------------- padded prefix offsets ----------------
__global__ void offsets_kernel() {
    if (threadIdx.x == 0 && blockIdx.x == 0) {
        int o = 0;
        for (int e = 0; e < E_NUM; e++) {
            g_off[e] = o;
            o += ((g_cnt[e] + BM - 1) / BM) * BM;
        }
        g_off[E_NUM] = o;
    }
}

// ---------------- scatter ----------------
__global__ __launch_bounds__(256) void scatter_kernel() {
    int t = blockIdx.x * blockDim.x + threadIdx.x;
    if (t >= T_TOK) return;
#pragma unroll
    for (int k = 0; k < K_TOP; k++) {
        int e = g_tok_e[2 * t + k];
        int r = g_off[e] + atomicAdd(&g_cnt2[e], 1);
        g_row_token[r] = t;
        g_row_scale[r] = g_tok_s[2 * t + k];
        g_tok_row[2 * t + k] = r;
    }
}

// =========================================================================
// Grouped TF32 tensor-core GEMMs: 128x128x32 tile, 8 warps x (32x64),
// mma.sync.m16n8k8, register-prefetch over single SMEM buffer.
// =========================================================================

// ---- GEMM1: h = relu(xn[gather] @ wi[e]),  K = D_DIM, N = FF_DIM ----
__global__ __launch_bounds__(256) void gemm1_kernel(const float* __restrict__ wi) {
    int r0 = blockIdx.y * BM;
    int n0 = blockIdx.x * BN;
    if (g_row_token[r0] < 0) return;      // padded/unused tile

    int e = 0;
    while (r0 >= g_off[e + 1]) e++;
    const float* Bg = wi + (size_t)e * D_DIM * FF_DIM;

    __shared__ float As[BM][BK + 4];      // [128][36] : frag reads conflict-free
    __shared__ float Bs[BK][BN + 4];      // [32][132]

    int tid  = threadIdx.x;
    int wid  = tid >> 5, lane = tid & 31;
    int wm   = wid & 3,  wn   = wid >> 2;     // 4x2 warp grid
    int gid  = lane >> 2, tg  = lane & 3;

    // A gather pointers
    int arow  = tid >> 1, ahalf = tid & 1;
    int atok  = g_row_token[r0 + arow];
    const float* aptr = g_xn + (size_t)(atok >= 0 ? atok : 0) * D_DIM + ahalf * 16;
    // B pointers
    int brow = tid >> 3;
    int bcol = (tid & 7) * 16;
    const float* bptr = Bg + (size_t)brow * FF_DIM + n0 + bcol;

    float c[2][8][4];
#pragma unroll
    for (int mt = 0; mt < 2; mt++)
#pragma unroll
        for (int nt = 0; nt < 8; nt++)
#pragma unroll
            for (int i = 0; i < 4; i++) c[mt][nt][i] = 0.0f;

    float4 pa[4], pb[4];
#pragma unroll
    for (int j = 0; j < 4; j++) {
        pa[j] = *(const float4*)(aptr + j * 4);
        pb[j] = *(const float4*)(bptr + (size_t)j * 0 + j * 4);
    }
    // (pb loads 16 consecutive floats of one B row)

    for (int k0 = 0; k0 < D_DIM; k0 += BK) {
#pragma unroll
        for (int j = 0; j < 4; j++) {
            *(float4*)&As[arow][ahalf * 16 + j * 4] = cvt4(pa[j]);
            *(float4*)&Bs[brow][bcol + j * 4]       = cvt4(pb[j]);
        }
        __syncthreads();

        if (k0 + BK < D_DIM) {
#pragma unroll
            for (int j = 0; j < 4; j++) {
                pa[j] = *(const float4*)(aptr + (k0 + BK) + j * 4);
                pb[j] = *(const float4*)(bptr + (size_t)(k0 + BK) * FF_DIM + j * 4);
            }
        }

#pragma unroll
        for (int kk = 0; kk < BK; kk += 8) {
            unsigned a[2][4];
#pragma unroll
            for (int mt = 0; mt < 2; mt++) {
                int row = wm * 32 + mt * 16 + gid;
                a[mt][0] = __float_as_uint(As[row    ][kk + tg    ]);
                a[mt][1] = __float_as_uint(As[row + 8][kk + tg    ]);
                a[mt][2] = __float_as_uint(As[row    ][kk + tg + 4]);
                a[mt][3] = __float_as_uint(As[row + 8][kk + tg + 4]);
            }
            unsigned b[8][2];
#pragma unroll
            for (int nt = 0; nt < 8; nt++) {
                int col = wn * 64 + nt * 8 + gid;
                b[nt][0] = __float_as_uint(Bs[kk + tg    ][col]);
                b[nt][1] = __float_as_uint(Bs[kk + tg + 4][col]);
            }
#pragma unroll
            for (int mt = 0; mt < 2; mt++)
#pragma unroll
                for (int nt = 0; nt < 8; nt++)
                    mma_tf32(c[mt][nt], a[mt], b[nt]);
        }
        __syncthreads();
    }

    // epilogue: relu, float2 stores
#pragma unroll
    for (int mt = 0; mt < 2; mt++) {
        int rA = r0 + wm * 32 + mt * 16 + gid;
#pragma unroll
        for (int nt = 0; nt < 8; nt++) {
            int col = n0 + wn * 64 + nt * 8 + tg * 2;
            float2 lo, hi;
            lo.x = fmaxf(c[mt][nt][0], 0.f); lo.y = fmaxf(c[mt][nt][1], 0.f);
            hi.x = fmaxf(c[mt][nt][2], 0.f); hi.y = fmaxf(c[mt][nt][3], 0.f);
            *(float2*)&g_h[(size_t)rA       * FF_DIM + col] = lo;
            *(float2*)&g_h[(size_t)(rA + 8) * FF_DIM + col] = hi;
        }
    }
}

// ---- GEMM2: y = scale * (h @ wo[e]),  K = FF_DIM, N = D_DIM ----
__global__ __launch_bounds__(256) void gemm2_kernel(const float* __restrict__ wo) {
    int r0 = blockIdx.y * BM;
    int n0 = blockIdx.x * BN;
    if (g_row_token[r0] < 0) return;

    int e = 0;
    while (r0 >= g_off[e + 1]) e++;
    const float* Bg = wo + (size_t)e * FF_DIM * D_DIM;

    __shared__ float As[BM][BK + 4];
    __shared__ float Bs[BK][BN + 4];

    int tid  = threadIdx.x;
    int wid  = tid >> 5, lane = tid & 31;
    int wm   = wid & 3,  wn   = wid >> 2;
    int gid  = lane >> 2, tg  = lane & 3;

    int arow  = tid >> 1, ahalf = tid & 1;
    const float* aptr = g_h + (size_t)(r0 + arow) * FF_DIM + ahalf * 16;
    int brow = tid >> 3;
    int bcol = (tid & 7) * 16;
    const float* bptr = Bg + (size_t)brow * D_DIM + n0 + bcol;

    float c[2][8][4];
#pragma unroll
    for (int mt = 0; mt < 2; mt++)
#pragma unroll
        for (int nt = 0; nt < 8; nt++)
#pragma unroll
            for (int i = 0; i < 4; i++) c[mt][nt][i] = 0.0f;

    float4 pa[4], pb[4];
#pragma unroll
    for (int j = 0; j < 4; j++) {
        pa[j] = *(const float4*)(aptr + j * 4);
        pb[j] = *(const float4*)(bptr + j * 4);
    }

    for (int k0 = 0; k0 < FF_DIM; k0 += BK) {
#pragma unroll
        for (int j = 0; j < 4; j++) {
            *(float4*)&As[arow][ahalf * 16 + j * 4] = cvt4(pa[j]);
            *(float4*)&Bs[brow][bcol + j * 4]       = cvt4(pb[j]);
        }
        __syncthreads();

        if (k0 + BK < FF_DIM) {
#pragma unroll
            for (int j = 0; j < 4; j++) {
                pa[j] = *(const float4*)(aptr + (k0 + BK) + j * 4);
                pb[j] = *(const float4*)(bptr + (size_t)(k0 + BK) * D_DIM + j * 4);
            }
        }

#pragma unroll
        for (int kk = 0; kk < BK; kk += 8) {
            unsigned a[2][4];
#pragma unroll
            for (int mt = 0; mt < 2; mt++) {
                int row = wm * 32 + mt * 16 + gid;
                a[mt][0] = __float_as_uint(As[row    ][kk + tg    ]);
                a[mt][1] = __float_as_uint(As[row + 8][kk + tg    ]);
                a[mt][2] = __float_as_uint(As[row    ][kk + tg + 4]);
                a[mt][3] = __float_as_uint(As[row + 8][kk + tg + 4]);
            }
            unsigned b[8][2];
#pragma unroll
            for (int nt = 0; nt < 8; nt++) {
                int col = wn * 64 + nt * 8 + gid;
                b[nt][0] = __float_as_uint(Bs[kk + tg    ][col]);
                b[nt][1] = __float_as_uint(Bs[kk + tg + 4][col]);
            }
#pragma unroll
            for (int mt = 0; mt < 2; mt++)
#pragma unroll
                for (int nt = 0; nt < 8; nt++)
                    mma_tf32(c[mt][nt], a[mt], b[nt]);
        }
        __syncthreads();
    }

#pragma unroll
    for (int mt = 0; mt < 2; mt++) {
        int rA = r0 + wm * 32 + mt * 16 + gid;
        float s0 = g_row_scale[rA];
        float s1 = g_row_scale[rA + 8];
#pragma unroll
        for (int nt = 0; nt < 8; nt++) {
            int col = n0 + wn * 64 + nt * 8 + tg * 2;
            float2 lo, hi;
            lo.x = s0 * c[mt][nt][0]; lo.y = s0 * c[mt][nt][1];
            hi.x = s1 * c[mt][nt][2]; hi.y = s1 * c[mt][nt][3];
            *(float2*)&g_y[(size_t)rA       * D_DIM + col] = lo;
            *(float2*)&g_y[(size_t)(rA + 8) * D_DIM + col] = hi;
        }
    }
}

// ---------------- combine ----------------
__global__ __launch_bounds__(256) void combine_kernel(const float* __restrict__ hidden,
                                                      float* __restrict__ out) {
    int i = blockIdx.x * blockDim.x + threadIdx.x;
    int t = i >> 8;
    int d4 = i & 255;
    int r0 = g_tok_row[2 * t + 0];
    int r1 = g_tok_row[2 * t + 1];
    float4 h  = ((const float4*)hidden)[i];
    float4 y0 = ((const float4*)(g_y + (size_t)r0 * D_DIM))[d4];
    float4 y1 = ((const float4*)(g_y + (size_t)r1 * D_DIM))[d4];
    float4 o;
    o.x = h.x + y0.x + y1.x;
    o.y = h.y + y0.y + y1.y;
    o.z = h.z + y0.z + y1.z;
    o.w = h.w + y0.w + y1.w;
    ((float4*)out)[i] = o;
}

// ---------------- launch ----------------
extern "C" void kernel_launch(void* const* d_in, const int* in_sizes, int n_in,
                              void* d_out, int out_size) {
    const float* hidden = (const float*)d_in[0];
    const float* ln_w   = (const float*)d_in[1];
    const float* gate_w = (const float*)d_in[2];
    const float* gate_b = (const float*)d_in[3];
    const float* wi     = (const float*)d_in[4];
    const float* wo     = (const float*)d_in[5];
    float* out = (float*)d_out;

    reset_kernel<<<(ROWS_MAX + 255) / 256, 256>>>();
    rmsnorm_kernel<<<T_TOK, 256>>>(hidden, ln_w);
    gate_kernel<<<T_TOK / 8, 256>>>(gate_w, gate_b);
    offsets_kernel<<<1, 32>>>();
    scatter_kernel<<<(T_TOK + 255) / 256, 256>>>();
    gemm1_kernel<<<dim3(FF_DIM / BN, ROWS_MAX / BM), 256>>>(wi);
    gemm2_kernel<<<dim3(D_DIM / BN, ROWS_MAX / BM), 256>>>(wo);
    combine_kernel<<<(T_TOK * D_DIM / 4) / 256, 256>>>(hidden, out);
}

// round 3
// speedup vs baseline: 2.6295x; 1.2770x over previous
#include <cuda_runtime.h>

// ---------------- problem constants ----------------
#define T_TOK   8192
#define D_DIM   1024
#define FF_DIM  4096
#define E_NUM   16
#define K_TOP   2
#define EPS     1e-6f

#define BM 128
#define BN 128
#define BK 16
#define ROWS_MAX 18432

// ---------------- scratch ----------------
__device__ float g_xn[(size_t)T_TOK * D_DIM];
__device__ float g_h [(size_t)ROWS_MAX * FF_DIM];
__device__ float g_y [(size_t)ROWS_MAX * D_DIM];
__device__ int   g_cnt [E_NUM];
__device__ int   g_cnt2[E_NUM];
__device__ int   g_off [E_NUM + 1];
__device__ int   g_row_token[ROWS_MAX];
__device__ float g_row_scale[ROWS_MAX];
__device__ int   g_tok_row[T_TOK * K_TOP];
__device__ int   g_tok_e  [T_TOK * K_TOP];
__device__ float g_tok_s  [T_TOK * K_TOP];

// ---------------- helpers ----------------
__device__ __forceinline__ void mma_tf32(float* c, const unsigned* a, const unsigned* b) {
    asm volatile(
        "mma.sync.aligned.m16n8k8.row.col.f32.tf32.tf32.f32 "
        "{%0,%1,%2,%3}, {%4,%5,%6,%7}, {%8,%9}, {%0,%1,%2,%3};"
        : "+f"(c[0]), "+f"(c[1]), "+f"(c[2]), "+f"(c[3])
        : "r"(a[0]), "r"(a[1]), "r"(a[2]), "r"(a[3]), "r"(b[0]), "r"(b[1]));
}
__device__ __forceinline__ void cp16(void* smem, const void* g) {
    unsigned s = (unsigned)__cvta_generic_to_shared(smem);
    asm volatile("cp.async.cg.shared.global [%0], [%1], 16;" :: "r"(s), "l"(g));
}
__device__ __forceinline__ void cp_commit() { asm volatile("cp.async.commit_group;"); }

// ---------------- reset ----------------
__global__ void reset_kernel() {
    int i = blockIdx.x * blockDim.x + threadIdx.x;
    if (i < ROWS_MAX) g_row_token[i] = -1;
    if (i < E_NUM) { g_cnt[i] = 0; g_cnt2[i] = 0; }
}

// ---------------- RMSNorm ----------------
__global__ __launch_bounds__(256) void rmsnorm_kernel(const float* __restrict__ x,
                                                      const float* __restrict__ w) {
    int t = blockIdx.x;
    int tid = threadIdx.x;
    const float4* xr = (const float4*)(x + (size_t)t * D_DIM);
    float4 v = xr[tid];
    float ss = v.x * v.x + v.y * v.y + v.z * v.z + v.w * v.w;

    __shared__ float red[256];
    red[tid] = ss;
    __syncthreads();
    for (int s = 128; s > 0; s >>= 1) {
        if (tid < s) red[tid] += red[tid + s];
        __syncthreads();
    }
    float inv = rsqrtf(red[0] * (1.0f / (float)D_DIM) + EPS);

    float4 wv = ((const float4*)w)[tid];
    float4 o;
    o.x = v.x * inv * wv.x;
    o.y = v.y * inv * wv.y;
    o.z = v.z * inv * wv.z;
    o.w = v.w * inv * wv.w;
    ((float4*)(g_xn + (size_t)t * D_DIM))[tid] = o;
}

// ---------------- gate ----------------
__global__ __launch_bounds__(256) void gate_kernel(const float* __restrict__ gw,
                                                   const float* __restrict__ gb) {
    int t = blockIdx.x * 8 + (threadIdx.x >> 5);
    int lane = threadIdx.x & 31;
    if (t >= T_TOK) return;

    float acc[E_NUM];
#pragma unroll
    for (int e = 0; e < E_NUM; e++) acc[e] = 0.0f;

    const float* xr = g_xn + (size_t)t * D_DIM;
    for (int d = lane; d < D_DIM; d += 32) {
        float xv = xr[d];
        const float4* wr = (const float4*)(gw + (size_t)d * E_NUM);
        float4 w0 = wr[0], w1 = wr[1], w2 = wr[2], w3 = wr[3];
        acc[0]  += xv * w0.x; acc[1]  += xv * w0.y; acc[2]  += xv * w0.z; acc[3]  += xv * w0.w;
        acc[4]  += xv * w1.x; acc[5]  += xv * w1.y; acc[6]  += xv * w1.z; acc[7]  += xv * w1.w;
        acc[8]  += xv * w2.x; acc[9]  += xv * w2.y; acc[10] += xv * w2.z; acc[11] += xv * w2.w;
        acc[12] += xv * w3.x; acc[13] += xv * w3.y; acc[14] += xv * w3.z; acc[15] += xv * w3.w;
    }
#pragma unroll
    for (int e = 0; e < E_NUM; e++) {
#pragma unroll
        for (int o = 16; o > 0; o >>= 1)
            acc[e] += __shfl_down_sync(0xFFFFFFFFu, acc[e], o);
    }

    if (lane == 0) {
        float v0 = -1e30f, v1 = -1e30f;
        int e0 = 0, e1 = 0;
#pragma unroll
        for (int e = 0; e < E_NUM; e++) {
            float val = acc[e] + gb[e];
            if (val > v0) { v1 = v0; e1 = e0; v0 = val; e0 = e; }
            else if (val > v1) { v1 = val; e1 = e; }
        }
        float ex = expf(v1 - v0);
        float s0 = 1.0f / (1.0f + ex);
        float s1 = ex * s0;
        g_tok_e[2 * t + 0] = e0; g_tok_s[2 * t + 0] = s0;
        g_tok_e[2 * t + 1] = e1; g_tok_s[2 * t + 1] = s1;
        atomicAdd(&g_cnt[e0], 1);
        atomicAdd(&g_cnt[e1], 1);
    }
}

// ---------------- offsets ----------------
__global__ void offsets_kernel() {
    if (threadIdx.x == 0 && blockIdx.x == 0) {
        int o = 0;
        for (int e = 0; e < E_NUM; e++) {
            g_off[e] = o;
            o += ((g_cnt[e] + BM - 1) / BM) * BM;
        }
        g_off[E_NUM] = o;
    }
}

// ---------------- scatter ----------------
__global__ __launch_bounds__(256) void scatter_kernel() {
    int t = blockIdx.x * blockDim.x + threadIdx.x;
    if (t >= T_TOK) return;
#pragma unroll
    for (int k = 0; k < K_TOP; k++) {
        int e = g_tok_e[2 * t + k];
        int r = g_off[e] + atomicAdd(&g_cnt2[e], 1);
        g_row_token[r] = t;
        g_row_scale[r] = g_tok_s[2 * t + k];
        g_tok_row[2 * t + k] = r;
    }
}

// =========================================================================
// Grouped TF32 GEMMs: 128x128 tile, BK=16, cp.async double-buffered,
// 8 warps x (32x64) via mma.m16n8k8, 2 blocks/SM.
// =========================================================================

// ---- GEMM1: h = relu(xn[gather] @ wi[e]) ----
__global__ __launch_bounds__(256, 2) void gemm1_kernel(const float* __restrict__ wi) {
    int r0 = blockIdx.y * BM;
    int n0 = blockIdx.x * BN;
    if (g_row_token[r0] < 0) return;

    int e = 0;
    while (r0 >= g_off[e + 1]) e++;
    const float* Bg = wi + (size_t)e * D_DIM * FF_DIM;

    __shared__ float As[2][BM][BK + 4];   // [2][128][20]
    __shared__ float Bs[2][BK][BN + 4];   // [2][16][132]

    int tid  = threadIdx.x;
    int wid  = tid >> 5, lane = tid & 31;
    int wm   = wid & 3,  wn   = wid >> 2;
    int gid  = lane >> 2, tg  = lane & 3;

    // A gather: each thread copies two float4 of one row-half
    int arow = tid >> 1, aseg = (tid & 1) * 8;
    int atok = g_row_token[r0 + arow];
    const float* aptr = g_xn + (size_t)(atok >= 0 ? atok : 0) * D_DIM + aseg;
    // B: brow 0..15, two float4 chunks per thread
    int brow = tid >> 4, bc0 = (tid & 15) * 4;
    const float* bptr = Bg + (size_t)brow * FF_DIM + n0;

    float c[2][8][4];
#pragma unroll
    for (int mt = 0; mt < 2; mt++)
#pragma unroll
        for (int nt = 0; nt < 8; nt++)
#pragma unroll
            for (int i = 0; i < 4; i++) c[mt][nt][i] = 0.0f;

    // prologue: stage 0
    {
        cp16(&As[0][arow][aseg],     aptr);
        cp16(&As[0][arow][aseg + 4], aptr + 4);
        cp16(&Bs[0][brow][bc0],      bptr + bc0);
        cp16(&Bs[0][brow][bc0 + 64], bptr + bc0 + 64);
        cp_commit();
    }

    int s = 0;
    for (int k0 = 0; k0 < D_DIM; k0 += BK, s ^= 1) {
        if (k0 + BK < D_DIM) {
            int kn = k0 + BK;
            cp16(&As[s ^ 1][arow][aseg],     aptr + kn);
            cp16(&As[s ^ 1][arow][aseg + 4], aptr + kn + 4);
            const float* bp = bptr + (size_t)kn * FF_DIM;
            cp16(&Bs[s ^ 1][brow][bc0],      bp + bc0);
            cp16(&Bs[s ^ 1][brow][bc0 + 64], bp + bc0 + 64);
            cp_commit();
            asm volatile("cp.async.wait_group 1;");
        } else {
            asm volatile("cp.async.wait_group 0;");
        }
        __syncthreads();

#pragma unroll
        for (int kk = 0; kk < BK; kk += 8) {
            unsigned a[2][4];
#pragma unroll
            for (int mt = 0; mt < 2; mt++) {
                int row = wm * 32 + mt * 16 + gid;
                a[mt][0] = __float_as_uint(As[s][row    ][kk + tg    ]);
                a[mt][1] = __float_as_uint(As[s][row + 8][kk + tg    ]);
                a[mt][2] = __float_as_uint(As[s][row    ][kk + tg + 4]);
                a[mt][3] = __float_as_uint(As[s][row + 8][kk + tg + 4]);
            }
            unsigned b[8][2];
#pragma unroll
            for (int nt = 0; nt < 8; nt++) {
                int col = wn * 64 + nt * 8 + gid;
                b[nt][0] = __float_as_uint(Bs[s][kk + tg    ][col]);
                b[nt][1] = __float_as_uint(Bs[s][kk + tg + 4][col]);
            }
#pragma unroll
            for (int mt = 0; mt < 2; mt++)
#pragma unroll
                for (int nt = 0; nt < 8; nt++)
                    mma_tf32(c[mt][nt], a[mt], b[nt]);
        }
        __syncthreads();
    }

#pragma unroll
    for (int mt = 0; mt < 2; mt++) {
        int rA = r0 + wm * 32 + mt * 16 + gid;
#pragma unroll
        for (int nt = 0; nt < 8; nt++) {
            int col = n0 + wn * 64 + nt * 8 + tg * 2;
            float2 lo, hi;
            lo.x = fmaxf(c[mt][nt][0], 0.f); lo.y = fmaxf(c[mt][nt][1], 0.f);
            hi.x = fmaxf(c[mt][nt][2], 0.f); hi.y = fmaxf(c[mt][nt][3], 0.f);
            *(float2*)&g_h[(size_t)rA       * FF_DIM + col] = lo;
            *(float2*)&g_h[(size_t)(rA + 8) * FF_DIM + col] = hi;
        }
    }
}

// ---- GEMM2: y = scale * (h @ wo[e]) ----
__global__ __launch_bounds__(256, 2) void gemm2_kernel(const float* __restrict__ wo) {
    int r0 = blockIdx.y * BM;
    int n0 = blockIdx.x * BN;
    if (g_row_token[r0] < 0) return;

    int e = 0;
    while (r0 >= g_off[e + 1]) e++;
    const float* Bg = wo + (size_t)e * FF_DIM * D_DIM;

    __shared__ float As[2][BM][BK + 4];
    __shared__ float Bs[2][BK][BN + 4];

    int tid  = threadIdx.x;
    int wid  = tid >> 5, lane = tid & 31;
    int wm   = wid & 3,  wn   = wid >> 2;
    int gid  = lane >> 2, tg  = lane & 3;

    int arow = tid >> 1, aseg = (tid & 1) * 8;
    const float* aptr = g_h + (size_t)(r0 + arow) * FF_DIM + aseg;
    int brow = tid >> 4, bc0 = (tid & 15) * 4;
    const float* bptr = Bg + (size_t)brow * D_DIM + n0;

    float c[2][8][4];
#pragma unroll
    for (int mt = 0; mt < 2; mt++)
#pragma unroll
        for (int nt = 0; nt < 8; nt++)
#pragma unroll
            for (int i = 0; i < 4; i++) c[mt][nt][i] = 0.0f;

    {
        cp16(&As[0][arow][aseg],     aptr);
        cp16(&As[0][arow][aseg + 4], aptr + 4);
        cp16(&Bs[0][brow][bc0],      bptr + bc0);
        cp16(&Bs[0][brow][bc0 + 64], bptr + bc0 + 64);
        cp_commit();
    }

    int s = 0;
    for (int k0 = 0; k0 < FF_DIM; k0 += BK, s ^= 1) {
        if (k0 + BK < FF_DIM) {
            int kn = k0 + BK;
            cp16(&As[s ^ 1][arow][aseg],     aptr + kn);
            cp16(&As[s ^ 1][arow][aseg + 4], aptr + kn + 4);
            const float* bp = bptr + (size_t)kn * D_DIM;
            cp16(&Bs[s ^ 1][brow][bc0],      bp + bc0);
            cp16(&Bs[s ^ 1][brow][bc0 + 64], bp + bc0 + 64);
            cp_commit();
            asm volatile("cp.async.wait_group 1;");
        } else {
            asm volatile("cp.async.wait_group 0;");
        }
        __syncthreads();

#pragma unroll
        for (int kk = 0; kk < BK; kk += 8) {
            unsigned a[2][4];
#pragma unroll
            for (int mt = 0; mt < 2; mt++) {
                int row = wm * 32 + mt * 16 + gid;
                a[mt][0] = __float_as_uint(As[s][row    ][kk + tg    ]);
                a[mt][1] = __float_as_uint(As[s][row + 8][kk + tg    ]);
                a[mt][2] = __float_as_uint(As[s][row    ][kk + tg + 4]);
                a[mt][3] = __float_as_uint(As[s][row + 8][kk + tg + 4]);
            }
            unsigned b[8][2];
#pragma unroll
            for (int nt = 0; nt < 8; nt++) {
                int col = wn * 64 + nt * 8 + gid;
                b[nt][0] = __float_as_uint(Bs[s][kk + tg    ][col]);
                b[nt][1] = __float_as_uint(Bs[s][kk + tg + 4][col]);
            }
#pragma unroll
            for (int mt = 0; mt < 2; mt++)
#pragma unroll
                for (int nt = 0; nt < 8; nt++)
                    mma_tf32(c[mt][nt], a[mt], b[nt]);
        }
        __syncthreads();
    }

#pragma unroll
    for (int mt = 0; mt < 2; mt++) {
        int rA = r0 + wm * 32 + mt * 16 + gid;
        float s0 = g_row_scale[rA];
        float s1 = g_row_scale[rA + 8];
#pragma unroll
        for (int nt = 0; nt < 8; nt++) {
            int col = n0 + wn * 64 + nt * 8 + tg * 2;
            float2 lo, hi;
            lo.x = s0 * c[mt][nt][0]; lo.y = s0 * c[mt][nt][1];
            hi.x = s1 * c[mt][nt][2]; hi.y = s1 * c[mt][nt][3];
            *(float2*)&g_y[(size_t)rA       * D_DIM + col] = lo;
            *(float2*)&g_y[(size_t)(rA + 8) * D_DIM + col] = hi;
        }
    }
}

// ---------------- combine ----------------
__global__ __launch_bounds__(256) void combine_kernel(const float* __restrict__ hidden,
                                                      float* __restrict__ out) {
    int i = blockIdx.x * blockDim.x + threadIdx.x;
    int t = i >> 8;
    int d4 = i & 255;
    int r0 = g_tok_row[2 * t + 0];
    int r1 = g_tok_row[2 * t + 1];
    float4 h  = ((const float4*)hidden)[i];
    float4 y0 = ((const float4*)(g_y + (size_t)r0 * D_DIM))[d4];
    float4 y1 = ((const float4*)(g_y + (size_t)r1 * D_DIM))[d4];
    float4 o;
    o.x = h.x + y0.x + y1.x;
    o.y = h.y + y0.y + y1.y;
    o.z = h.z + y0.z + y1.z;
    o.w = h.w + y0.w + y1.w;
    ((float4*)out)[i] = o;
}

// ---------------- launch ----------------
extern "C" void kernel_launch(void* const* d_in, const int* in_sizes, int n_in,
                              void* d_out, int out_size) {
    const float* hidden = (const float*)d_in[0];
    const float* ln_w   = (const float*)d_in[1];
    const float* gate_w = (const float*)d_in[2];
    const float* gate_b = (const float*)d_in[3];
    const float* wi     = (const float*)d_in[4];
    const float* wo     = (const float*)d_in[5];
    float* out = (float*)d_out;

    reset_kernel<<<(ROWS_MAX + 255) / 256, 256>>>();
    rmsnorm_kernel<<<T_TOK, 256>>>(hidden, ln_w);
    gate_kernel<<<T_TOK / 8, 256>>>(gate_w, gate_b);
    offsets_kernel<<<1, 32>>>();
    scatter_kernel<<<(T_TOK + 255) / 256, 256>>>();
    gemm1_kernel<<<dim3(FF_DIM / BN, ROWS_MAX / BM), 256>>>(wi);
    gemm2_kernel<<<dim3(D_DIM / BN, ROWS_MAX / BM), 256>>>(wo);
    combine_kernel<<<(T_TOK * D_DIM / 4) / 256, 256>>>(hidden, out);
}

// round 5
// speedup vs baseline: 3.2664x; 1.2422x over previous
#include <cuda_runtime.h>
#include <cstdint>

// ---------------- problem constants ----------------
#define T_TOK   8192
#define D_DIM   1024
#define FF_DIM  4096
#define E_NUM   16
#define K_TOP   2
#define EPS     1e-6f

#define BM 128
#define BN 128
#define BK 32
#define ROWS_MAX 18432

// dynamic smem: As[2][128][36] + Bs[2][32][132] floats
#define AS_STRIDE 36
#define BS_STRIDE 132
#define AS_STAGE  (BM * AS_STRIDE)      // 4608 floats
#define BS_STAGE  (BK * BS_STRIDE)      // 4224 floats
#define SMEM_DYN  ((2 * AS_STAGE + 2 * BS_STAGE) * 4)   // 70656 bytes

// ---------------- scratch ----------------
__device__ float g_xn[(size_t)T_TOK * D_DIM];
__device__ float g_h [(size_t)ROWS_MAX * FF_DIM];
__device__ float g_y [(size_t)ROWS_MAX * D_DIM];
__device__ int   g_cnt [E_NUM];
__device__ int   g_cnt2[E_NUM];
__device__ int   g_off [E_NUM + 1];
__device__ int   g_row_token[ROWS_MAX];
__device__ float g_row_scale[ROWS_MAX];
__device__ int   g_tok_row[T_TOK * K_TOP];
__device__ int   g_tok_e  [T_TOK * K_TOP];
__device__ float g_tok_s  [T_TOK * K_TOP];

// ---------------- helpers ----------------
__device__ __forceinline__ unsigned rna_bits(float x) {
    unsigned r;
    asm("cvt.rna.tf32.f32 %0, %1;" : "=r"(r) : "f"(x));
    return r;
}
__device__ __forceinline__ void mma_tf32(float* c, const unsigned* a, const unsigned* b) {
    asm volatile(
        "mma.sync.aligned.m16n8k8.row.col.f32.tf32.tf32.f32 "
        "{%0,%1,%2,%3}, {%4,%5,%6,%7}, {%8,%9}, {%0,%1,%2,%3};"
        : "+f"(c[0]), "+f"(c[1]), "+f"(c[2]), "+f"(c[3])
        : "r"(a[0]), "r"(a[1]), "r"(a[2]), "r"(a[3]), "r"(b[0]), "r"(b[1]));
}
__device__ __forceinline__ void cp16(void* smem, const void* g) {
    unsigned s = (unsigned)__cvta_generic_to_shared(smem);
    asm volatile("cp.async.cg.shared.global [%0], [%1], 16;" :: "r"(s), "l"(g));
}
__device__ __forceinline__ void cp_commit() { asm volatile("cp.async.commit_group;" ::: "memory"); }

// ---------------- reset ----------------
__global__ void reset_kernel() {
    int i = blockIdx.x * blockDim.x + threadIdx.x;
    if (i < ROWS_MAX) g_row_token[i] = -1;
    if (i < E_NUM) { g_cnt[i] = 0; g_cnt2[i] = 0; }
}

// ---------------- RMSNorm ----------------
__global__ __launch_bounds__(256) void rmsnorm_kernel(const float* __restrict__ x,
                                                      const float* __restrict__ w) {
    int t = blockIdx.x;
    int tid = threadIdx.x;
    const float4* xr = (const float4*)(x + (size_t)t * D_DIM);
    float4 v = xr[tid];
    float ss = v.x * v.x + v.y * v.y + v.z * v.z + v.w * v.w;

    __shared__ float red[256];
    red[tid] = ss;
    __syncthreads();
    for (int s = 128; s > 0; s >>= 1) {
        if (tid < s) red[tid] += red[tid + s];
        __syncthreads();
    }
    float inv = rsqrtf(red[0] * (1.0f / (float)D_DIM) + EPS);

    float4 wv = ((const float4*)w)[tid];
    float4 o;
    o.x = v.x * inv * wv.x;
    o.y = v.y * inv * wv.y;
    o.z = v.z * inv * wv.z;
    o.w = v.w * inv * wv.w;
    ((float4*)(g_xn + (size_t)t * D_DIM))[tid] = o;
}

// ---------------- gate ----------------
__global__ __launch_bounds__(256) void gate_kernel(const float* __restrict__ gw,
                                                   const float* __restrict__ gb) {
    int t = blockIdx.x * 8 + (threadIdx.x >> 5);
    int lane = threadIdx.x & 31;
    if (t >= T_TOK) return;

    float acc[E_NUM];
#pragma unroll
    for (int e = 0; e < E_NUM; e++) acc[e] = 0.0f;

    const float* xr = g_xn + (size_t)t * D_DIM;
    for (int d = lane; d < D_DIM; d += 32) {
        float xv = xr[d];
        const float4* wr = (const float4*)(gw + (size_t)d * E_NUM);
        float4 w0 = wr[0], w1 = wr[1], w2 = wr[2], w3 = wr[3];
        acc[0]  += xv * w0.x; acc[1]  += xv * w0.y; acc[2]  += xv * w0.z; acc[3]  += xv * w0.w;
        acc[4]  += xv * w1.x; acc[5]  += xv * w1.y; acc[6]  += xv * w1.z; acc[7]  += xv * w1.w;
        acc[8]  += xv * w2.x; acc[9]  += xv * w2.y; acc[10] += xv * w2.z; acc[11] += xv * w2.w;
        acc[12] += xv * w3.x; acc[13] += xv * w3.y; acc[14] += xv * w3.z; acc[15] += xv * w3.w;
    }
#pragma unroll
    for (int e = 0; e < E_NUM; e++) {
#pragma unroll
        for (int o = 16; o > 0; o >>= 1)
            acc[e] += __shfl_down_sync(0xFFFFFFFFu, acc[e], o);
    }

    if (lane == 0) {
        float v0 = -1e30f, v1 = -1e30f;
        int e0 = 0, e1 = 0;
#pragma unroll
        for (int e = 0; e < E_NUM; e++) {
            float val = acc[e] + gb[e];
            if (val > v0) { v1 = v0; e1 = e0; v0 = val; e0 = e; }
            else if (val > v1) { v1 = val; e1 = e; }
        }
        float ex = expf(v1 - v0);
        float s0 = 1.0f / (1.0f + ex);
        float s1 = ex * s0;
        g_tok_e[2 * t + 0] = e0; g_tok_s[2 * t + 0] = s0;
        g_tok_e[2 * t + 1] = e1; g_tok_s[2 * t + 1] = s1;
        atomicAdd(&g_cnt[e0], 1);
        atomicAdd(&g_cnt[e1], 1);
    }
}

// ---------------- offsets ----------------
__global__ void offsets_kernel() {
    if (threadIdx.x == 0 && blockIdx.x == 0) {
        int o = 0;
        for (int e = 0; e < E_NUM; e++) {
            g_off[e] = o;
            o += ((g_cnt[e] + BM - 1) / BM) * BM;
        }
        g_off[E_NUM] = o;
    }
}

// ---------------- scatter ----------------
__global__ __launch_bounds__(256) void scatter_kernel() {
    int t = blockIdx.x * blockDim.x + threadIdx.x;
    if (t >= T_TOK) return;
#pragma unroll
    for (int k = 0; k < K_TOP; k++) {
        int e = g_tok_e[2 * t + k];
        int r = g_off[e] + atomicAdd(&g_cnt2[e], 1);
        g_row_token[r] = t;
        g_row_scale[r] = g_tok_s[2 * t + k];
        g_tok_row[2 * t + k] = r;
    }
}

// =========================================================================
// Grouped TF32 GEMMs: 128x128 tile, BK=32 double-buffered cp.async in
// dynamic SMEM, 8 warps x (32x64) mma.m16n8k8, rna-rounded fragments,
// 2 CTAs/SM.
// MODE 0: g_h[r] = relu(A_gather @ wi[e])   (K=D_DIM,  N=FF_DIM)
// MODE 1: g_y[r] = scale * (g_h @ wo[e])    (K=FF_DIM, N=D_DIM)
// =========================================================================
template<int MODE>
__global__ __launch_bounds__(256, 2) void moe_gemm_kernel(const float* __restrict__ W) {
    constexpr int KT   = (MODE == 0) ? D_DIM : FF_DIM;
    constexpr int NTOT = (MODE == 0) ? FF_DIM : D_DIM;
    constexpr int T    = KT / BK;

    int r0 = blockIdx.y * BM;
    int n0 = blockIdx.x * BN;
    if (g_row_token[r0] < 0) return;

    int e = 0;
    while (r0 >= g_off[e + 1]) e++;
    const float* Bg = W + (size_t)e * D_DIM * FF_DIM;

    extern __shared__ float sm[];
    float* As = sm;                         // [2][BM][36]
    float* Bs = sm + 2 * AS_STAGE;          // [2][BK][132]

    __shared__ int s_tok[BM];

    int tid  = threadIdx.x;
    int wid  = tid >> 5, lane = tid & 31;
    int wm   = wid & 3,  wn   = wid >> 2;
    int gid  = lane >> 2, tg  = lane & 3;

    if (MODE == 0 && tid < BM) {
        int tk = g_row_token[r0 + tid];
        s_tok[tid] = tk < 0 ? 0 : tk;
    }
    __syncthreads();

    // ---- loaders: stage s gets K-columns [kt*BK, kt*BK+BK) ----
    auto load_stage = [&](int kt, int s) {
        int k0 = kt * BK;
        // A: 128 rows x 32 floats = 1024 float4; 4 per thread
#pragma unroll
        for (int j = 0; j < 4; j++) {
            int c = tid + 256 * j;
            int row = c >> 3;
            int seg = (c & 7) * 4;
            const float* src;
            if (MODE == 0) src = g_xn + (size_t)s_tok[row] * D_DIM + k0 + seg;
            else           src = g_h  + (size_t)(r0 + row) * FF_DIM + k0 + seg;
            cp16(&As[s * AS_STAGE + row * AS_STRIDE + seg], src);
        }
        // B: 32 rows x 128 floats = 1024 float4; 4 per thread
#pragma unroll
        for (int j = 0; j < 4; j++) {
            int c = tid + 256 * j;
            int row = c >> 5;
            int seg = (c & 31) * 4;
            const float* src = Bg + (size_t)(k0 + row) * NTOT + n0 + seg;
            cp16(&Bs[s * BS_STAGE + row * BS_STRIDE + seg], src);
        }
        cp_commit();
    };

    float c[2][8][4];
#pragma unroll
    for (int mt = 0; mt < 2; mt++)
#pragma unroll
        for (int nt = 0; nt < 8; nt++)
#pragma unroll
            for (int i = 0; i < 4; i++) c[mt][nt][i] = 0.0f;

    load_stage(0, 0);
    load_stage(1, 1);

    for (int i = 0; i < T; i++) {
        int s = i & 1;
        if (i + 1 < T) asm volatile("cp.async.wait_group 1;" ::: "memory");
        else           asm volatile("cp.async.wait_group 0;" ::: "memory");
        __syncthreads();

        const float* Ast = As + s * AS_STAGE;
        const float* Bst = Bs + s * BS_STAGE;
#pragma unroll
        for (int kk = 0; kk < BK; kk += 8) {
            unsigned a[2][4];
#pragma unroll
            for (int mt = 0; mt < 2; mt++) {
                int row = wm * 32 + mt * 16 + gid;
                a[mt][0] = rna_bits(Ast[row * AS_STRIDE + kk + tg]);
                a[mt][1] = rna_bits(Ast[(row + 8) * AS_STRIDE + kk + tg]);
                a[mt][2] = rna_bits(Ast[row * AS_STRIDE + kk + tg + 4]);
                a[mt][3] = rna_bits(Ast[(row + 8) * AS_STRIDE + kk + tg + 4]);
            }
            unsigned b[8][2];
#pragma unroll
            for (int nt = 0; nt < 8; nt++) {
                int col = wn * 64 + nt * 8 + gid;
                b[nt][0] = rna_bits(Bst[(kk + tg) * BS_STRIDE + col]);
                b[nt][1] = rna_bits(Bst[(kk + tg + 4) * BS_STRIDE + col]);
            }
#pragma unroll
            for (int mt = 0; mt < 2; mt++)
#pragma unroll
                for (int nt = 0; nt < 8; nt++)
                    mma_tf32(c[mt][nt], a[mt], b[nt]);
        }
        __syncthreads();

        if (i + 2 < T) load_stage(i + 2, s);
    }

    // ---- epilogue ----
#pragma unroll
    for (int mt = 0; mt < 2; mt++) {
        int rA = r0 + wm * 32 + mt * 16 + gid;
        if (MODE == 0) {
#pragma unroll
            for (int nt = 0; nt < 8; nt++) {
                int col = n0 + wn * 64 + nt * 8 + tg * 2;
                float2 lo, hi;
                lo.x = fmaxf(c[mt][nt][0], 0.f); lo.y = fmaxf(c[mt][nt][1], 0.f);
                hi.x = fmaxf(c[mt][nt][2], 0.f); hi.y = fmaxf(c[mt][nt][3], 0.f);
                *(float2*)&g_h[(size_t)rA       * FF_DIM + col] = lo;
                *(float2*)&g_h[(size_t)(rA + 8) * FF_DIM + col] = hi;
            }
        } else {
            float s0 = g_row_scale[rA];
            float s1 = g_row_scale[rA + 8];
#pragma unroll
            for (int nt = 0; nt < 8; nt++) {
                int col = n0 + wn * 64 + nt * 8 + tg * 2;
                float2 lo, hi;
                lo.x = s0 * c[mt][nt][0]; lo.y = s0 * c[mt][nt][1];
                hi.x = s1 * c[mt][nt][2]; hi.y = s1 * c[mt][nt][3];
                *(float2*)&g_y[(size_t)rA       * D_DIM + col] = lo;
                *(float2*)&g_y[(size_t)(rA + 8) * D_DIM + col] = hi;
            }
        }
    }
}

// ---------------- combine ----------------
__global__ __launch_bounds__(256) void combine_kernel(const float* __restrict__ hidden,
                                                      float* __restrict__ out) {
    int i = blockIdx.x * blockDim.x + threadIdx.x;
    int t = i >> 8;
    int d4 = i & 255;
    int r0 = g_tok_row[2 * t + 0];
    int r1 = g_tok_row[2 * t + 1];
    float4 h  = ((const float4*)hidden)[i];
    float4 y0 = ((const float4*)(g_y + (size_t)r0 * D_DIM))[d4];
    float4 y1 = ((const float4*)(g_y + (size_t)r1 * D_DIM))[d4];
    float4 o;
    o.x = h.x + y0.x + y1.x;
    o.y = h.y + y0.y + y1.y;
    o.z = h.z + y0.z + y1.z;
    o.w = h.w + y0.w + y1.w;
    ((float4*)out)[i] = o;
}

// ---------------- launch ----------------
extern "C" void kernel_launch(void* const* d_in, const int* in_sizes, int n_in,
                              void* d_out, int out_size) {
    const float* hidden = (const float*)d_in[0];
    const float* ln_w   = (const float*)d_in[1];
    const float* gate_w = (const float*)d_in[2];
    const float* gate_b = (const float*)d_in[3];
    const float* wi     = (const float*)d_in[4];
    const float* wo     = (const float*)d_in[5];
    float* out = (float*)d_out;

    static int configured = 0;
    if (!configured) {
        cudaFuncSetAttribute(moe_gemm_kernel<0>, cudaFuncAttributeMaxDynamicSharedMemorySize, SMEM_DYN);
        cudaFuncSetAttribute(moe_gemm_kernel<1>, cudaFuncAttributeMaxDynamicSharedMemorySize, SMEM_DYN);
        configured = 1;
    }

    reset_kernel<<<(ROWS_MAX + 255) / 256, 256>>>();
    rmsnorm_kernel<<<T_TOK, 256>>>(hidden, ln_w);
    gate_kernel<<<T_TOK / 8, 256>>>(gate_w, gate_b);
    offsets_kernel<<<1, 32>>>();
    scatter_kernel<<<(T_TOK + 255) / 256, 256>>>();
    moe_gemm_kernel<0><<<dim3(FF_DIM / BN, ROWS_MAX / BM), 256, SMEM_DYN>>>(wi);
    moe_gemm_kernel<1><<<dim3(D_DIM / BN, ROWS_MAX / BM), 256, SMEM_DYN>>>(wo);
    combine_kernel<<<(T_TOK * D_DIM / 4) / 256, 256>>>(hidden, out);
}

// round 6
// speedup vs baseline: 3.6765x; 1.1256x over previous
#include <cuda_runtime.h>
#include <cstdint>

// ---------------- problem constants ----------------
#define T_TOK   8192
#define D_DIM   1024
#define FF_DIM  4096
#define E_NUM   16
#define K_TOP   2
#define EPS     1e-6f

#define BM 128
#define BN 128
#define BK 32
#define ROWS_MAX 18432

#define AS_STRIDE 36
#define BS_STRIDE 132
#define AS_STAGE  (BM * AS_STRIDE)
#define BS_STAGE  (BK * BS_STRIDE)
#define SMEM_DYN  ((2 * AS_STAGE + 2 * BS_STAGE) * 4)   // 70656 bytes

// ---------------- scratch ----------------
__device__ float g_xn [(size_t)T_TOK * D_DIM];                  // fp32 for gate
__device__ float g_xnr[(size_t)T_TOK * D_DIM];                  // tf32-rounded for GEMM1
__device__ float g_h  [(size_t)ROWS_MAX * FF_DIM];              // tf32-rounded hidden
__device__ float g_y  [(size_t)ROWS_MAX * D_DIM];
__device__ float g_wir[(size_t)E_NUM * D_DIM * FF_DIM];         // tf32-rounded wi
__device__ float g_wor[(size_t)E_NUM * FF_DIM * D_DIM];         // tf32-rounded wo
__device__ int   g_cnt [E_NUM];
__device__ int   g_cnt2[E_NUM];
__device__ int   g_off [E_NUM + 1];
__device__ int   g_row_token[ROWS_MAX];
__device__ float g_row_scale[ROWS_MAX];
__device__ int   g_tok_row[T_TOK * K_TOP];
__device__ int   g_tok_e  [T_TOK * K_TOP];
__device__ float g_tok_s  [T_TOK * K_TOP];

// ---------------- helpers ----------------
__device__ __forceinline__ float rna_tf32(float x) {
    unsigned r;
    asm("cvt.rna.tf32.f32 %0, %1;" : "=r"(r) : "f"(x));
    return __uint_as_float(r);
}
__device__ __forceinline__ void mma_tf32(float* c, const unsigned* a, const unsigned* b) {
    asm volatile(
        "mma.sync.aligned.m16n8k8.row.col.f32.tf32.tf32.f32 "
        "{%0,%1,%2,%3}, {%4,%5,%6,%7}, {%8,%9}, {%0,%1,%2,%3};"
        : "+f"(c[0]), "+f"(c[1]), "+f"(c[2]), "+f"(c[3])
        : "r"(a[0]), "r"(a[1]), "r"(a[2]), "r"(a[3]), "r"(b[0]), "r"(b[1]));
}
__device__ __forceinline__ void cp16(void* smem, const void* g) {
    unsigned s = (unsigned)__cvta_generic_to_shared(smem);
    asm volatile("cp.async.cg.shared.global [%0], [%1], 16;" :: "r"(s), "l"(g));
}
__device__ __forceinline__ void cp_commit() { asm volatile("cp.async.commit_group;" ::: "memory"); }

// ---------------- weight rounding pass ----------------
__global__ __launch_bounds__(256) void round_weights_kernel(const float* __restrict__ src,
                                                            float* __restrict__ dst) {
    size_t i = (size_t)blockIdx.x * blockDim.x + threadIdx.x;   // float4 index
    float4 v = ((const float4*)src)[i];
    float4 o;
    o.x = rna_tf32(v.x); o.y = rna_tf32(v.y);
    o.z = rna_tf32(v.z); o.w = rna_tf32(v.w);
    ((float4*)dst)[i] = o;
}

// ---------------- reset ----------------
__global__ void reset_kernel() {
    int i = blockIdx.x * blockDim.x + threadIdx.x;
    if (i < ROWS_MAX) g_row_token[i] = -1;
    if (i < E_NUM) { g_cnt[i] = 0; g_cnt2[i] = 0; }
}

// ---------------- RMSNorm ----------------
__global__ __launch_bounds__(256) void rmsnorm_kernel(const float* __restrict__ x,
                                                      const float* __restrict__ w) {
    int t = blockIdx.x;
    int tid = threadIdx.x;
    const float4* xr = (const float4*)(x + (size_t)t * D_DIM);
    float4 v = xr[tid];
    float ss = v.x * v.x + v.y * v.y + v.z * v.z + v.w * v.w;

    __shared__ float red[256];
    red[tid] = ss;
    __syncthreads();
    for (int s = 128; s > 0; s >>= 1) {
        if (tid < s) red[tid] += red[tid + s];
        __syncthreads();
    }
    float inv = rsqrtf(red[0] * (1.0f / (float)D_DIM) + EPS);

    float4 wv = ((const float4*)w)[tid];
    float4 o;
    o.x = v.x * inv * wv.x;
    o.y = v.y * inv * wv.y;
    o.z = v.z * inv * wv.z;
    o.w = v.w * inv * wv.w;
    ((float4*)(g_xn + (size_t)t * D_DIM))[tid] = o;
    float4 r;
    r.x = rna_tf32(o.x); r.y = rna_tf32(o.y); r.z = rna_tf32(o.z); r.w = rna_tf32(o.w);
    ((float4*)(g_xnr + (size_t)t * D_DIM))[tid] = r;
}

// ---------------- gate (raw fp32 activations) ----------------
__global__ __launch_bounds__(256) void gate_kernel(const float* __restrict__ gw,
                                                   const float* __restrict__ gb) {
    int t = blockIdx.x * 8 + (threadIdx.x >> 5);
    int lane = threadIdx.x & 31;
    if (t >= T_TOK) return;

    float acc[E_NUM];
#pragma unroll
    for (int e = 0; e < E_NUM; e++) acc[e] = 0.0f;

    const float* xr = g_xn + (size_t)t * D_DIM;
    for (int d = lane; d < D_DIM; d += 32) {
        float xv = xr[d];
        const float4* wr = (const float4*)(gw + (size_t)d * E_NUM);
        float4 w0 = wr[0], w1 = wr[1], w2 = wr[2], w3 = wr[3];
        acc[0]  += xv * w0.x; acc[1]  += xv * w0.y; acc[2]  += xv * w0.z; acc[3]  += xv * w0.w;
        acc[4]  += xv * w1.x; acc[5]  += xv * w1.y; acc[6]  += xv * w1.z; acc[7]  += xv * w1.w;
        acc[8]  += xv * w2.x; acc[9]  += xv * w2.y; acc[10] += xv * w2.z; acc[11] += xv * w2.w;
        acc[12] += xv * w3.x; acc[13] += xv * w3.y; acc[14] += xv * w3.z; acc[15] += xv * w3.w;
    }
#pragma unroll
    for (int e = 0; e < E_NUM; e++) {
#pragma unroll
        for (int o = 16; o > 0; o >>= 1)
            acc[e] += __shfl_down_sync(0xFFFFFFFFu, acc[e], o);
    }

    if (lane == 0) {
        float v0 = -1e30f, v1 = -1e30f;
        int e0 = 0, e1 = 0;
#pragma unroll
        for (int e = 0; e < E_NUM; e++) {
            float val = acc[e] + gb[e];
            if (val > v0) { v1 = v0; e1 = e0; v0 = val; e0 = e; }
            else if (val > v1) { v1 = val; e1 = e; }
        }
        float ex = expf(v1 - v0);
        float s0 = 1.0f / (1.0f + ex);
        float s1 = ex * s0;
        g_tok_e[2 * t + 0] = e0; g_tok_s[2 * t + 0] = s0;
        g_tok_e[2 * t + 1] = e1; g_tok_s[2 * t + 1] = s1;
        atomicAdd(&g_cnt[e0], 1);
        atomicAdd(&g_cnt[e1], 1);
    }
}

// ---------------- offsets ----------------
__global__ void offsets_kernel() {
    if (threadIdx.x == 0 && blockIdx.x == 0) {
        int o = 0;
        for (int e = 0; e < E_NUM; e++) {
            g_off[e] = o;
            o += ((g_cnt[e] + BM - 1) / BM) * BM;
        }
        g_off[E_NUM] = o;
    }
}

// ---------------- scatter ----------------
__global__ __launch_bounds__(256) void scatter_kernel() {
    int t = blockIdx.x * blockDim.x + threadIdx.x;
    if (t >= T_TOK) return;
#pragma unroll
    for (int k = 0; k < K_TOP; k++) {
        int e = g_tok_e[2 * t + k];
        int r = g_off[e] + atomicAdd(&g_cnt2[e], 1);
        g_row_token[r] = t;
        g_row_scale[r] = g_tok_s[2 * t + k];
        g_tok_row[2 * t + k] = r;
    }
}

// =========================================================================
// Grouped TF32 GEMMs, pre-rounded operands (no in-loop cvt):
// 128 threads = 4 warps in 2x2 grid, each warp owns 64x64 (mt=4, nt=8).
// BK=32 double-buffered cp.async, distance-2 prefetch, 2 CTAs/SM.
// MODE 0: g_h[r] = rna(relu(A_gather @ g_wir[e]))   (K=D,  N=FF)
// MODE 1: g_y[r] = scale * (g_h @ g_wor[e])         (K=FF, N=D)
// =========================================================================
template<int MODE>
__global__ __launch_bounds__(128, 2) void moe_gemm_kernel() {
    constexpr int KT   = (MODE == 0) ? D_DIM : FF_DIM;
    constexpr int NTOT = (MODE == 0) ? FF_DIM : D_DIM;
    constexpr int T    = KT / BK;

    int r0 = blockIdx.y * BM;
    int n0 = blockIdx.x * BN;
    if (g_row_token[r0] < 0) return;

    int e = 0;
    while (r0 >= g_off[e + 1]) e++;
    const float* Bg = ((MODE == 0) ? g_wir : g_wor) + (size_t)e * D_DIM * FF_DIM;

    extern __shared__ float sm[];
    float* As = sm;                         // [2][BM][36]
    float* Bs = sm + 2 * AS_STAGE;          // [2][BK][132]

    __shared__ int s_tok[BM];

    int tid  = threadIdx.x;
    int wid  = tid >> 5, lane = tid & 31;
    int wm   = wid & 1,  wn   = wid >> 1;       // 2x2 warp grid
    int gid  = lane >> 2, tg  = lane & 3;

    if (MODE == 0) {
        int tk = g_row_token[r0 + tid];
        s_tok[tid] = tk < 0 ? 0 : tk;
    }
    __syncthreads();

    auto load_stage = [&](int kt, int s) {
        int k0 = kt * BK;
        // A: 128 rows x 32 floats = 1024 float4; 8 per thread
#pragma unroll
        for (int j = 0; j < 8; j++) {
            int c = tid + 128 * j;
            int row = c >> 3;
            int seg = (c & 7) * 4;
            const float* src;
            if (MODE == 0) src = g_xnr + (size_t)s_tok[row] * D_DIM + k0 + seg;
            else           src = g_h   + (size_t)(r0 + row) * FF_DIM + k0 + seg;
            cp16(&As[s * AS_STAGE + row * AS_STRIDE + seg], src);
        }
        // B: 32 rows x 128 floats = 1024 float4; 8 per thread
#pragma unroll
        for (int j = 0; j < 8; j++) {
            int c = tid + 128 * j;
            int row = c >> 5;
            int seg = (c & 31) * 4;
            const float* src = Bg + (size_t)(k0 + row) * NTOT + n0 + seg;
            cp16(&Bs[s * BS_STAGE + row * BS_STRIDE + seg], src);
        }
        cp_commit();
    };

    float c[4][8][4];
#pragma unroll
    for (int mt = 0; mt < 4; mt++)
#pragma unroll
        for (int nt = 0; nt < 8; nt++)
#pragma unroll
            for (int i = 0; i < 4; i++) c[mt][nt][i] = 0.0f;

    load_stage(0, 0);
    load_stage(1, 1);

    for (int i = 0; i < T; i++) {
        int s = i & 1;
        if (i + 1 < T) asm volatile("cp.async.wait_group 1;" ::: "memory");
        else           asm volatile("cp.async.wait_group 0;" ::: "memory");
        __syncthreads();

        const float* Ast = As + s * AS_STAGE;
        const float* Bst = Bs + s * BS_STAGE;
#pragma unroll
        for (int kk = 0; kk < BK; kk += 8) {
            unsigned a[4][4];
#pragma unroll
            for (int mt = 0; mt < 4; mt++) {
                int row = wm * 64 + mt * 16 + gid;
                a[mt][0] = __float_as_uint(Ast[row * AS_STRIDE + kk + tg]);
                a[mt][1] = __float_as_uint(Ast[(row + 8) * AS_STRIDE + kk + tg]);
                a[mt][2] = __float_as_uint(Ast[row * AS_STRIDE + kk + tg + 4]);
                a[mt][3] = __float_as_uint(Ast[(row + 8) * AS_STRIDE + kk + tg + 4]);
            }
            unsigned b[8][2];
#pragma unroll
            for (int nt = 0; nt < 8; nt++) {
                int col = wn * 64 + nt * 8 + gid;
                b[nt][0] = __float_as_uint(Bst[(kk + tg) * BS_STRIDE + col]);
                b[nt][1] = __float_as_uint(Bst[(kk + tg + 4) * BS_STRIDE + col]);
            }
#pragma unroll
            for (int mt = 0; mt < 4; mt++)
#pragma unroll
                for (int nt = 0; nt < 8; nt++)
                    mma_tf32(c[mt][nt], a[mt], b[nt]);
        }
        __syncthreads();

        if (i + 2 < T) load_stage(i + 2, s);
    }

    // ---- epilogue ----
#pragma unroll
    for (int mt = 0; mt < 4; mt++) {
        int rA = r0 + wm * 64 + mt * 16 + gid;
        if (MODE == 0) {
#pragma unroll
            for (int nt = 0; nt < 8; nt++) {
                int col = n0 + wn * 64 + nt * 8 + tg * 2;
                float2 lo, hi;
                lo.x = rna_tf32(fmaxf(c[mt][nt][0], 0.f));
                lo.y = rna_tf32(fmaxf(c[mt][nt][1], 0.f));
                hi.x = rna_tf32(fmaxf(c[mt][nt][2], 0.f));
                hi.y = rna_tf32(fmaxf(c[mt][nt][3], 0.f));
                *(float2*)&g_h[(size_t)rA       * FF_DIM + col] = lo;
                *(float2*)&g_h[(size_t)(rA + 8) * FF_DIM + col] = hi;
            }
        } else {
            float s0 = g_row_scale[rA];
            float s1 = g_row_scale[rA + 8];
#pragma unroll
            for (int nt = 0; nt < 8; nt++) {
                int col = n0 + wn * 64 + nt * 8 + tg * 2;
                float2 lo, hi;
                lo.x = s0 * c[mt][nt][0]; lo.y = s0 * c[mt][nt][1];
                hi.x = s1 * c[mt][nt][2]; hi.y = s1 * c[mt][nt][3];
                *(float2*)&g_y[(size_t)rA       * D_DIM + col] = lo;
                *(float2*)&g_y[(size_t)(rA + 8) * D_DIM + col] = hi;
            }
        }
    }
}

// ---------------- combine ----------------
__global__ __launch_bounds__(256) void combine_kernel(const float* __restrict__ hidden,
                                                      float* __restrict__ out) {
    int i = blockIdx.x * blockDim.x + threadIdx.x;
    int t = i >> 8;
    int d4 = i & 255;
    int r0 = g_tok_row[2 * t + 0];
    int r1 = g_tok_row[2 * t + 1];
    float4 h  = ((const float4*)hidden)[i];
    float4 y0 = ((const float4*)(g_y + (size_t)r0 * D_DIM))[d4];
    float4 y1 = ((const float4*)(g_y + (size_t)r1 * D_DIM))[d4];
    float4 o;
    o.x = h.x + y0.x + y1.x;
    o.y = h.y + y0.y + y1.y;
    o.z = h.z + y0.z + y1.z;
    o.w = h.w + y0.w + y1.w;
    ((float4*)out)[i] = o;
}

// ---------------- launch ----------------
extern "C" void kernel_launch(void* const* d_in, const int* in_sizes, int n_in,
                              void* d_out, int out_size) {
    const float* hidden = (const float*)d_in[0];
    const float* ln_w   = (const float*)d_in[1];
    const float* gate_w = (const float*)d_in[2];
    const float* gate_b = (const float*)d_in[3];
    const float* wi     = (const float*)d_in[4];
    const float* wo     = (const float*)d_in[5];
    float* out = (float*)d_out;

    static int configured = 0;
    if (!configured) {
        cudaFuncSetAttribute(moe_gemm_kernel<0>, cudaFuncAttributeMaxDynamicSharedMemorySize, SMEM_DYN);
        cudaFuncSetAttribute(moe_gemm_kernel<1>, cudaFuncAttributeMaxDynamicSharedMemorySize, SMEM_DYN);
        configured = 1;
    }

    const size_t WFLOAT4 = (size_t)E_NUM * D_DIM * FF_DIM / 4;   // 16.78M float4

    // weight rounding passes (independent of token path)
    float* wir; cudaGetSymbolAddress((void**)&wir, g_wir);
    float* wor; cudaGetSymbolAddress((void**)&wor, g_wor);
    round_weights_kernel<<<(unsigned)(WFLOAT4 / 256), 256>>>(wi, wir);
    round_weights_kernel<<<(unsigned)(WFLOAT4 / 256), 256>>>(wo, wor);

    reset_kernel<<<(ROWS_MAX + 255) / 256, 256>>>();
    rmsnorm_kernel<<<T_TOK, 256>>>(hidden, ln_w);
    gate_kernel<<<T_TOK / 8, 256>>>(gate_w, gate_b);
    offsets_kernel<<<1, 32>>>();
    scatter_kernel<<<(T_TOK + 255) / 256, 256>>>();
    moe_gemm_kernel<0><<<dim3(FF_DIM / BN, ROWS_MAX / BM), 128, SMEM_DYN>>>();
    moe_gemm_kernel<1><<<dim3(D_DIM / BN, ROWS_MAX / BM), 128, SMEM_DYN>>>();
    combine_kernel<<<(T_TOK * D_DIM / 4) / 256, 256>>>(hidden, out);
}